// round 14
// baseline (speedup 1.0000x reference)
#include <cuda_runtime.h>
#include <cstdint>

#define NN 50000
#define IN_FT 256
#define OUT_FT 64
#define NE 800000
#define NRT 3125          // row tiles of 16: 3125*16 = 50000 exactly
#define NKS 16            // k-steps of 16
#define NGB 391           // gemm blocks: ceil(3125/8)
#define NEB 3125          // edge blocks: 3125*256 = 800000 exactly
#define CAP 96            // per-dst bin capacity (Poisson(16): P(>96) ~ e^-60)
#define WF_BYTES (NKS * 8 * 32 * 16)   // 64 KB of W fragments

// ---------------- device scratch (no allocations allowed) -------------------
// g_cnt self-zeroing invariant: statically zero-initialized, and
// gather_kernel re-zeroes every entry during every execution.
__device__ float g_fts[NN * OUT_FT];             // fc(seq) result, 12.8 MB
__device__ int   g_cnt[NN];                      // degree counters (0 at entry)
__device__ int2  g_edge[NN * CAP];               // binned edges (src, val-bits)

// ---- split fp32 -> (hi bf16x2, lo bf16x2) ----------------------------------
__device__ __forceinline__ void split2(float x0, float x1,
                                       uint32_t& h, uint32_t& l) {
    asm("cvt.rn.bf16x2.f32 %0, %1, %2;" : "=r"(h) : "f"(x1), "f"(x0));
    float h0 = __uint_as_float(h << 16);
    float h1 = __uint_as_float(h & 0xFFFF0000u);
    asm("cvt.rn.bf16x2.f32 %0, %1, %2;" : "=r"(l) : "f"(x1 - h1), "f"(x0 - h0));
}

// ---- mma.sync m16n8k16 bf16: acc += A * B ----------------------------------
__device__ __forceinline__ void mma16816(float* c, const uint32_t* a,
                                         uint32_t b0, uint32_t b1) {
    asm volatile(
        "mma.sync.aligned.m16n8k16.row.col.f32.bf16.bf16.f32 "
        "{%0,%1,%2,%3}, {%4,%5,%6,%7}, {%8,%9}, {%0,%1,%2,%3};"
        : "+f"(c[0]), "+f"(c[1]), "+f"(c[2]), "+f"(c[3])
        : "r"(a[0]), "r"(a[1]), "r"(a[2]), "r"(a[3]), "r"(b0), "r"(b1));
}

// ---------------------------------------------------------------------------
// K1: blocks 0..NGB-1: convert W -> bf16 hi/lo fragments in SMEM, then run
// the tensor-pipe GEMM (split-bf16 mma.sync, 1 warp = 16 rows).
// Blocks NGB..: bin edges (hist+fill in one pass, capacity layout).
// ---------------------------------------------------------------------------
__global__ __launch_bounds__(256) void main_kernel(
    const float* __restrict__ seq, const float* __restrict__ W,
    float* __restrict__ fts,
    const int* __restrict__ esrc, const int* __restrict__ edst,
    const float* __restrict__ eval)
{
    if (blockIdx.x >= NGB) {
        // ---- edge binning ----
        int e = (blockIdx.x - NGB) * 256 + threadIdx.x;
        if (e < NE) {
            int d = edst[e];
            int r = atomicAdd(&g_cnt[d], 1);
            if (r < CAP)
                g_edge[d * CAP + r] = make_int2(esrc[e], __float_as_int(eval[e]));
        }
        return;
    }

    // ---- GEMM block: convert W fragments into smem (layout [ks][nt][lane]) --
    extern __shared__ uint4 s_wf[];
    {
        int t = threadIdx.x;
#pragma unroll
        for (int i = 0; i < 16; i++) {
            int idx  = t + i * 256;           // 0..4095
            int ks   = idx >> 8;
            int rem  = idx & 255;
            int nt   = rem >> 5;
            int lane = rem & 31;
            int n    = nt * 8 + (lane >> 2);
            int k    = ks * 16 + (lane & 3) * 2;
            float2 w0 = *(const float2*)&W[n * IN_FT + k];
            float2 w1 = *(const float2*)&W[n * IN_FT + k + 8];
            uint32_t b0h, b0l, b1h, b1l;
            split2(w0.x, w0.y, b0h, b0l);
            split2(w1.x, w1.y, b1h, b1l);
            s_wf[idx] = make_uint4(b0h, b1h, b0l, b1l);
        }
    }
    __syncthreads();

    int wid  = threadIdx.x >> 5;
    int lane = threadIdx.x & 31;
    int rt   = blockIdx.x * 8 + wid;
    if (rt >= NRT) return;
    int g  = lane >> 2;
    int tg = lane & 3;

    const float* ar0 = seq + (size_t)(rt * 16 + g) * IN_FT;
    const float* ar1 = ar0 + 8 * IN_FT;

    float acc[8][4];
#pragma unroll
    for (int nt = 0; nt < 8; nt++)
#pragma unroll
        for (int i = 0; i < 4; i++) acc[nt][i] = 0.0f;

#pragma unroll
    for (int ks = 0; ks < NKS; ks++) {
        int k0 = ks * 16 + tg * 2;
        float2 x0 = *(const float2*)&ar0[k0];
        float2 x1 = *(const float2*)&ar1[k0];
        float2 x2 = *(const float2*)&ar0[k0 + 8];
        float2 x3 = *(const float2*)&ar1[k0 + 8];

        uint32_t ah[4], al[4];
        split2(x0.x, x0.y, ah[0], al[0]);
        split2(x1.x, x1.y, ah[1], al[1]);
        split2(x2.x, x2.y, ah[2], al[2]);
        split2(x3.x, x3.y, ah[3], al[3]);

        const uint4* wp = s_wf + ks * 256 + lane;
#pragma unroll
        for (int nt = 0; nt < 8; nt++) {
            uint4 b = wp[nt * 32];             // conflict-free LDS.128
            mma16816(acc[nt], ah, b.x, b.y);   // Ah*Bh
            mma16816(acc[nt], al, b.x, b.y);   // Al*Bh
            mma16816(acc[nt], ah, b.z, b.w);   // Ah*Bl
        }
    }

    float* o0 = fts + (size_t)(rt * 16 + g) * OUT_FT + tg * 2;
    float* o1 = o0 + 8 * OUT_FT;
#pragma unroll
    for (int nt = 0; nt < 8; nt++) {
        *(float2*)(o0 + nt * 8) = make_float2(acc[nt][0], acc[nt][1]);
        *(float2*)(o1 + nt * 8) = make_float2(acc[nt][2], acc[nt][3]);
    }
}

// ---------------------------------------------------------------------------
// K2: gather (R10 structure, proven): 16 lanes per dst, 16 dsts per block,
// 4-way unrolled. Re-zeroes g_cnt[d]. Single write per output element
// (un-poisons d_out).
// ---------------------------------------------------------------------------
__global__ __launch_bounds__(256) void gather_kernel(
    const float4* __restrict__ fts4,
    const float* __restrict__ bias, const float* __restrict__ alpha,
    float4* __restrict__ out4)
{
    int t = threadIdx.x;
    int d = blockIdx.x * 16 + (t >> 4);
    int j = t & 15;
    if (d >= NN) return;

    int n = g_cnt[d];
    if (n > CAP) n = CAP;
    if (j == 0) g_cnt[d] = 0;             // restore invariant for next call
    const int2* ep = g_edge + (size_t)d * CAP;

    float4 a0 = make_float4(0.f, 0.f, 0.f, 0.f);
    float4 a1 = make_float4(0.f, 0.f, 0.f, 0.f);
    float4 a2 = make_float4(0.f, 0.f, 0.f, 0.f);
    float4 a3 = make_float4(0.f, 0.f, 0.f, 0.f);

    int e = 0;
    for (; e + 3 < n; e += 4) {
        int2 e0 = ep[e];
        int2 e1 = ep[e + 1];
        int2 e2 = ep[e + 2];
        int2 e3 = ep[e + 3];
        float4 f0 = __ldg(&fts4[(size_t)e0.x * 16 + j]);
        float4 f1 = __ldg(&fts4[(size_t)e1.x * 16 + j]);
        float4 f2 = __ldg(&fts4[(size_t)e2.x * 16 + j]);
        float4 f3 = __ldg(&fts4[(size_t)e3.x * 16 + j]);
        float v0 = __int_as_float(e0.y), v1 = __int_as_float(e1.y);
        float v2 = __int_as_float(e2.y), v3 = __int_as_float(e3.y);
        a0.x += f0.x * v0; a0.y += f0.y * v0; a0.z += f0.z * v0; a0.w += f0.w * v0;
        a1.x += f1.x * v1; a1.y += f1.y * v1; a1.z += f1.z * v1; a1.w += f1.w * v1;
        a2.x += f2.x * v2; a2.y += f2.y * v2; a2.z += f2.z * v2; a2.w += f2.w * v2;
        a3.x += f3.x * v3; a3.y += f3.y * v3; a3.z += f3.z * v3; a3.w += f3.w * v3;
    }
    for (; e < n; e++) {
        int2 e0 = ep[e];
        float v0 = __int_as_float(e0.y);
        float4 f0 = __ldg(&fts4[(size_t)e0.x * 16 + j]);
        a0.x += f0.x * v0; a0.y += f0.y * v0; a0.z += f0.z * v0; a0.w += f0.w * v0;
    }

    float4 bb = ((const float4*)bias)[j];
    float  al = __ldg(&alpha[0]);
    float4 r;
    r.x = (a0.x + a1.x) + (a2.x + a3.x) + bb.x;
    r.y = (a0.y + a1.y) + (a2.y + a3.y) + bb.y;
    r.z = (a0.z + a1.z) + (a2.z + a3.z) + bb.z;
    r.w = (a0.w + a1.w) + (a2.w + a3.w) + bb.w;
    r.x = (r.x >= 0.f) ? r.x : al * r.x;
    r.y = (r.y >= 0.f) ? r.y : al * r.y;
    r.z = (r.z >= 0.f) ? r.z : al * r.z;
    r.w = (r.w >= 0.f) ? r.w : al * r.w;
    out4[(size_t)d * 16 + j] = r;
}

extern "C" void kernel_launch(void* const* d_in, const int* in_sizes, int n_in,
                              void* d_out, int out_size)
{
    const float* seq   = (const float*)d_in[0];
    const float* W     = (const float*)d_in[1];
    const float* bias  = (const float*)d_in[2];
    const float* alpha = (const float*)d_in[3];
    const int*   esrc  = (const int*)d_in[4];
    const int*   edst  = (const int*)d_in[5];
    const float* eval  = (const float*)d_in[6];
    float* out = (float*)d_out;

    float* fts;
    cudaGetSymbolAddress((void**)&fts, g_fts);

    static bool attr_set = false;
    if (!attr_set) {
        cudaFuncSetAttribute(main_kernel,
                             cudaFuncAttributeMaxDynamicSharedMemorySize, WF_BYTES);
        attr_set = true;
    }

    // K1: [GEMM with in-block W conversion] || [edge binning]
    main_kernel<<<NGB + NEB, 256, WF_BYTES>>>(seq, W, fts, esrc, edst, eval);

    // K2: gather + bias + PReLU (+ counter re-zero)
    gather_kernel<<<(NN + 15) / 16, 256>>>((const float4*)fts, bias, alpha,
                                           (float4*)out);
}

// round 15
// speedup vs baseline: 1.7013x; 1.7013x over previous
#include <cuda_runtime.h>
#include <cstdint>

#define NN 50000
#define IN_FT 256
#define OUT_FT 64
#define NE 800000
#define NRT 3125          // row tiles of 16: 3125*16 = 50000 exactly
#define NKS 16            // k-steps of 16
#define NGB 391           // gemm blocks: ceil(3125/8)
#define NEB 3125          // edge blocks: 3125*256 = 800000 exactly
#define CAP 96            // per-dst bin capacity (Poisson(16): P(>96) ~ e^-60)

// ---------------- device scratch (no allocations allowed) -------------------
__device__ float g_fts[NN * OUT_FT];             // fc(seq) result, 12.8 MB
__device__ uint4 g_wf[NKS * 8 * 32];             // W fragments, 64 KB
__device__ int   g_cnt[NN];                      // degree counters
__device__ int2  g_edge[NN * CAP];               // binned edges (src, val-bits)

// ---- split fp32 -> (hi bf16x2, lo bf16x2) ----------------------------------
__device__ __forceinline__ void split2(float x0, float x1,
                                       uint32_t& h, uint32_t& l) {
    asm("cvt.rn.bf16x2.f32 %0, %1, %2;" : "=r"(h) : "f"(x1), "f"(x0));
    float h0 = __uint_as_float(h << 16);
    float h1 = __uint_as_float(h & 0xFFFF0000u);
    asm("cvt.rn.bf16x2.f32 %0, %1, %2;" : "=r"(l) : "f"(x1 - h1), "f"(x0 - h0));
}

// ---- mma.sync m16n8k16 bf16: acc += A * B ----------------------------------
__device__ __forceinline__ void mma16816(float* c, const uint32_t* a,
                                         uint32_t b0, uint32_t b1) {
    asm volatile(
        "mma.sync.aligned.m16n8k16.row.col.f32.bf16.bf16.f32 "
        "{%0,%1,%2,%3}, {%4,%5,%6,%7}, {%8,%9}, {%0,%1,%2,%3};"
        : "+f"(c[0]), "+f"(c[1]), "+f"(c[2]), "+f"(c[3])
        : "r"(a[0]), "r"(a[1]), "r"(a[2]), "r"(a[3]), "r"(b0), "r"(b1));
}

// ---------------------------------------------------------------------------
// K1: blocks 0..15 convert W to fragments; blocks 16.. zero the counters.
// ---------------------------------------------------------------------------
__global__ void prep_kernel(const float* __restrict__ W)
{
    if (blockIdx.x < NKS) {
        int ks   = blockIdx.x;
        int nt   = threadIdx.x >> 5;
        int lane = threadIdx.x & 31;
        int g    = lane >> 2;
        int tg   = lane & 3;
        int n    = nt * 8 + g;
        int k    = ks * 16 + tg * 2;

        float2 w0 = *(const float2*)&W[n * IN_FT + k];
        float2 w1 = *(const float2*)&W[n * IN_FT + k + 8];
        uint32_t b0h, b0l, b1h, b1l;
        split2(w0.x, w0.y, b0h, b0l);
        split2(w1.x, w1.y, b1h, b1l);
        g_wf[(ks * 8 + nt) * 32 + lane] = make_uint4(b0h, b1h, b0l, b1l);
    } else {
        int i = (blockIdx.x - NKS) * 256 + threadIdx.x;
        if (i < NN) g_cnt[i] = 0;
    }
}

// ---------------------------------------------------------------------------
// K2: blocks 0..NGB-1 run the tensor-pipe GEMM (split-bf16 mma.sync,
// 1 warp = 16 rows); blocks NGB.. bin the edges (hist+fill in one pass,
// capacity layout -> no prefix scan needed).
// ---------------------------------------------------------------------------
__global__ __launch_bounds__(256) void main_kernel(
    const float* __restrict__ seq, float* __restrict__ fts,
    const int* __restrict__ esrc, const int* __restrict__ edst,
    const float* __restrict__ eval)
{
    if (blockIdx.x >= NGB) {
        // ---- edge binning ----
        int e = (blockIdx.x - NGB) * 256 + threadIdx.x;
        if (e < NE) {
            int d = edst[e];
            int r = atomicAdd(&g_cnt[d], 1);
            if (r < CAP)
                g_edge[d * CAP + r] = make_int2(esrc[e], __float_as_int(eval[e]));
        }
        return;
    }

    // ---- GEMM ----
    int wid  = threadIdx.x >> 5;
    int lane = threadIdx.x & 31;
    int rt   = blockIdx.x * 8 + wid;
    if (rt >= NRT) return;
    int g  = lane >> 2;
    int tg = lane & 3;

    const float* ar0 = seq + (size_t)(rt * 16 + g) * IN_FT;
    const float* ar1 = ar0 + 8 * IN_FT;

    float acc[8][4];
#pragma unroll
    for (int nt = 0; nt < 8; nt++)
#pragma unroll
        for (int i = 0; i < 4; i++) acc[nt][i] = 0.0f;

#pragma unroll
    for (int ks = 0; ks < NKS; ks++) {
        int k0 = ks * 16 + tg * 2;
        float2 x0 = *(const float2*)&ar0[k0];
        float2 x1 = *(const float2*)&ar1[k0];
        float2 x2 = *(const float2*)&ar0[k0 + 8];
        float2 x3 = *(const float2*)&ar1[k0 + 8];

        uint32_t ah[4], al[4];
        split2(x0.x, x0.y, ah[0], al[0]);
        split2(x1.x, x1.y, ah[1], al[1]);
        split2(x2.x, x2.y, ah[2], al[2]);
        split2(x3.x, x3.y, ah[3], al[3]);

        const uint4* wp = g_wf + ks * 256 + lane;
#pragma unroll
        for (int nt = 0; nt < 8; nt++) {
            uint4 b = __ldg(wp + nt * 32);
            mma16816(acc[nt], ah, b.x, b.y);   // Ah*Bh
            mma16816(acc[nt], al, b.x, b.y);   // Al*Bh
            mma16816(acc[nt], ah, b.z, b.w);   // Ah*Bl
        }
    }

    float* o0 = fts + (size_t)(rt * 16 + g) * OUT_FT + tg * 2;
    float* o1 = o0 + 8 * OUT_FT;
#pragma unroll
    for (int nt = 0; nt < 8; nt++) {
        *(float2*)(o0 + nt * 8) = make_float2(acc[nt][0], acc[nt][1]);
        *(float2*)(o1 + nt * 8) = make_float2(acc[nt][2], acc[nt][3]);
    }
}

// ---------------------------------------------------------------------------
// K3: gather (R10 structure — proven local optimum): 16 lanes per dst,
// 16 dsts per 256-block, 4 independent fts row-loads in flight. Edge
// stream read as paired LDG.128 (two edges per load; g_edge bins are
// 16B-aligned since CAP*8=768). Single write per output element.
// ---------------------------------------------------------------------------
__global__ __launch_bounds__(256) void gather_kernel(
    const float4* __restrict__ fts4,
    const float* __restrict__ bias, const float* __restrict__ alpha,
    float4* __restrict__ out4)
{
    int t = threadIdx.x;
    int d = blockIdx.x * 16 + (t >> 4);
    int j = t & 15;
    if (d >= NN) return;

    int n = g_cnt[d];
    if (n > CAP) n = CAP;
    const int2* ep  = g_edge + (size_t)d * CAP;
    const int4* ep4 = (const int4*)ep;

    float4 a0 = make_float4(0.f, 0.f, 0.f, 0.f);
    float4 a1 = make_float4(0.f, 0.f, 0.f, 0.f);
    float4 a2 = make_float4(0.f, 0.f, 0.f, 0.f);
    float4 a3 = make_float4(0.f, 0.f, 0.f, 0.f);

    int e = 0;
    for (; e + 3 < n; e += 4) {
        int4 q0 = ep4[(e >> 1) + 0];       // edges e, e+1
        int4 q1 = ep4[(e >> 1) + 1];       // edges e+2, e+3
        float4 f0 = __ldg(&fts4[(size_t)q0.x * 16 + j]);
        float4 f1 = __ldg(&fts4[(size_t)q0.z * 16 + j]);
        float4 f2 = __ldg(&fts4[(size_t)q1.x * 16 + j]);
        float4 f3 = __ldg(&fts4[(size_t)q1.z * 16 + j]);
        float v0 = __int_as_float(q0.y), v1 = __int_as_float(q0.w);
        float v2 = __int_as_float(q1.y), v3 = __int_as_float(q1.w);
        a0.x += f0.x * v0; a0.y += f0.y * v0; a0.z += f0.z * v0; a0.w += f0.w * v0;
        a1.x += f1.x * v1; a1.y += f1.y * v1; a1.z += f1.z * v1; a1.w += f1.w * v1;
        a2.x += f2.x * v2; a2.y += f2.y * v2; a2.z += f2.z * v2; a2.w += f2.w * v2;
        a3.x += f3.x * v3; a3.y += f3.y * v3; a3.z += f3.z * v3; a3.w += f3.w * v3;
    }
    for (; e < n; e++) {
        int2 e0 = ep[e];
        float v0 = __int_as_float(e0.y);
        float4 f0 = __ldg(&fts4[(size_t)e0.x * 16 + j]);
        a0.x += f0.x * v0; a0.y += f0.y * v0; a0.z += f0.z * v0; a0.w += f0.w * v0;
    }

    float4 bb = ((const float4*)bias)[j];
    float  al = __ldg(&alpha[0]);
    float4 r;
    r.x = (a0.x + a1.x) + (a2.x + a3.x) + bb.x;
    r.y = (a0.y + a1.y) + (a2.y + a3.y) + bb.y;
    r.z = (a0.z + a1.z) + (a2.z + a3.z) + bb.z;
    r.w = (a0.w + a1.w) + (a2.w + a3.w) + bb.w;
    r.x = (r.x >= 0.f) ? r.x : al * r.x;
    r.y = (r.y >= 0.f) ? r.y : al * r.y;
    r.z = (r.z >= 0.f) ? r.z : al * r.z;
    r.w = (r.w >= 0.f) ? r.w : al * r.w;
    out4[(size_t)d * 16 + j] = r;
}

extern "C" void kernel_launch(void* const* d_in, const int* in_sizes, int n_in,
                              void* d_out, int out_size)
{
    const float* seq   = (const float*)d_in[0];
    const float* W     = (const float*)d_in[1];
    const float* bias  = (const float*)d_in[2];
    const float* alpha = (const float*)d_in[3];
    const int*   esrc  = (const int*)d_in[4];
    const int*   edst  = (const int*)d_in[5];
    const float* eval  = (const float*)d_in[6];
    float* out = (float*)d_out;

    float* fts;
    cudaGetSymbolAddress((void**)&fts, g_fts);

    // K1: wconv || zero counters
    prep_kernel<<<NKS + (NN + 255) / 256, 256>>>(W);

    // K2: GEMM || edge binning (independent, co-scheduled)
    main_kernel<<<NGB + NEB, 256>>>(seq, fts, esrc, edst, eval);

    // K3: gather + bias + PReLU
    gather_kernel<<<(NN + 15) / 16, 256>>>((const float4*)fts, bias, alpha,
                                           (float4*)out);
}